// round 12
// baseline (speedup 1.0000x reference)
#include <cuda_runtime.h>
#include <cuda_bf16.h>
#include <math.h>
#include <stdint.h>

// Problem constants
static constexpr int kB  = 64;      // batch
static constexpr int kT  = 1024;    // time steps
static constexpr int kF  = 512;     // input features
static constexpr int kU  = 1024;    // hidden units
static constexpr int k4U = 4096;    // 4*U
static constexpr int kC  = 1000;    // classes

static constexpr int NFUSED = 128;  // fused LSTM CTAs
static constexpr int NBG    = 20;   // background xz K-tail CTAs
static constexpr int NCTA   = NFUSED + NBG;   // 148
static constexpr int NTHR   = 256;  // 8 warps

// xz K split: fused producers kcg < 24 (K<384); background kcg 24..31
static constexpr int KHG  = 24;     // producer kcg count
static constexpr int BGK  = 8;      // bg kcg count
static constexpr int BGK0 = 24;     // bg kcg base

// SMEM layout (u32 units)
static constexpr int OFF_WRF   = 0;        // 16384 u32 (64 KB)
static constexpr int OFF_WKF   = 16384;    // 24*4*32 uint2 = 6144 u32
static constexpr int OFF_RING  = 22528;    // 4 x 64 x 34 fp32 = 8704 u32
static constexpr int OFF_BIAS  = 31232;    // 32 fp32
static constexpr int OFF_FLAGS = 31264;    // prod_done[4], cons_done[4]
static constexpr int SMEM_U32  = 31272;    // 125088 bytes
// bg role reuses fsm[0..]: 26*8*32 uint2 = 13312 u32 < SMEM_U32

// Scratch (device globals)
__device__ uint4    g_xf[(size_t)kT * 4096];            // x A-frags, 67 MB
__device__ float    g_xz2[(size_t)kT * 512 * 64 * 8];   // bg K-tail partials, 1 GB
__device__ uint32_t g_h[2 * 32768];                     // h ping-pong (bf16 frags)
__device__ unsigned g_cnt[8 * 32];                      // h group counters
__device__ unsigned g_bgcnt[NBG * 32];                  // bg step counters
__device__ float    g_lpart[4 * 64 * kC];               // logits partials, 1 MB

__device__ __forceinline__ uint32_t pack_bf16(float lo, float hi) {
    uint32_t r;
    asm("cvt.rn.bf16x2.f32 %0, %1, %2;" : "=r"(r) : "f"(hi), "f"(lo));
    return r;
}
__device__ __forceinline__ float tanh_fast(float x) {
    float r;
    asm("tanh.approx.f32 %0, %1;" : "=f"(r) : "f"(x));
    return r;
}
__device__ __forceinline__ float sigmoid_fast(float x) {
    return 1.f / (1.f + __expf(-x));
}
__device__ __forceinline__ void mma_bf16(float c[4], uint32_t a0, uint32_t a1,
                                         uint32_t a2, uint32_t a3,
                                         uint32_t b0, uint32_t b1) {
    asm volatile(
        "mma.sync.aligned.m16n8k16.row.col.f32.bf16.bf16.f32 "
        "{%0,%1,%2,%3},{%4,%5,%6,%7},{%8,%9},{%0,%1,%2,%3};"
        : "+f"(c[0]), "+f"(c[1]), "+f"(c[2]), "+f"(c[3])
        : "r"(a0), "r"(a1), "r"(a2), "r"(a3), "r"(b0), "r"(b1));
}
__device__ __forceinline__ void bar_named(int id, int cnt) {
    asm volatile("bar.sync %0, %1;" :: "r"(id), "r"(cnt) : "memory");
}
__device__ __forceinline__ unsigned ld_acq(const unsigned* p) {
    unsigned v;
    asm volatile("ld.acquire.gpu.u32 %0, [%1];" : "=r"(v) : "l"(p) : "memory");
    return v;
}
__device__ __forceinline__ unsigned poll_groups(int lane, unsigned tgt,
                                                unsigned rdy) {
    unsigned ok = 1u;
    if (lane < 8 && !((rdy >> lane) & 1u)) {
        unsigned v = ld_acq(&g_cnt[lane * 32]);
        ok = (v >= tgt) ? 1u : 0u;
    }
    return __ballot_sync(0xffffffffu, ok != 0u);
}

// ---------------------------------------------------------------------------
// Kernel 0: reset
// ---------------------------------------------------------------------------
__global__ void reset_kernel() {
    int idx = blockIdx.x * blockDim.x + threadIdx.x;
    if (idx < 8 * 32) g_cnt[idx] = 0u;
    if (idx < NBG * 32) g_bgcnt[idx] = 0u;
    for (int i = idx; i < 2 * 32768; i += gridDim.x * blockDim.x) g_h[i] = 0u;
}

// ---------------------------------------------------------------------------
// Kernel 1: permute x -> bf16 A-fragment order
// ---------------------------------------------------------------------------
__global__ __launch_bounds__(256) void permute_x(const float* __restrict__ x) {
    size_t idx = (size_t)blockIdx.x * 256 + threadIdx.x;   // < kT*4096
    int lane = idx & 31;
    int mt   = (idx >> 5) & 3;
    int kcg  = (idx >> 7) & 31;
    int t    = (int)(idx >> 12);
    int r  = mt * 16 + (lane >> 2);
    int k2 = kcg * 16 + 2 * (lane & 3);
    const float* x0 = x + ((size_t)r * kT + t) * kF;
    const float* x8 = x + ((size_t)(r + 8) * kT + t) * kF;
    float2 v00 = *(const float2*)(x0 + k2);
    float2 v10 = *(const float2*)(x8 + k2);
    float2 v01 = *(const float2*)(x0 + k2 + 8);
    float2 v11 = *(const float2*)(x8 + k2 + 8);
    uint4 o;
    o.x = pack_bf16(v00.x, v00.y);
    o.y = pack_bf16(v10.x, v10.y);
    o.z = pack_bf16(v01.x, v01.y);
    o.w = pack_bf16(v11.x, v11.y);
    g_xf[idx] = o;
}

// ---------------------------------------------------------------------------
// Kernel 2: persistent kernel, 148 CTAs.
//  CTAs 0..127 fused LSTM; CTAs 128..147 free-running xz K-tail (kcg 24..31).
// ---------------------------------------------------------------------------
extern __shared__ uint32_t fsm[];

__global__ __launch_bounds__(NTHR, 1) void lstm_fused(
    const float* __restrict__ Wr, const float* __restrict__ Wk,
    const float* __restrict__ bias) {
    const int tid = threadIdx.x;
    const int wid = tid >> 5, lid = tid & 31;

    if (blockIdx.x >= NFUSED) {
        // ================= BACKGROUND xz K-tail GEMM (8 kcg) =================
        const int j = blockIdx.x - NFUSED;
        const int n8_start = 26 * j;
        const int n8_cnt   = (512 - n8_start < 26) ? (512 - n8_start) : 26;
        uint2* Bs = (uint2*)fsm;             // [n8_cnt*8][32] uint2

        for (int i = tid; i < n8_cnt * BGK * 32; i += NTHR) {
            int lane = i & 31;
            int kcg  = (i >> 5) % BGK;
            int ni   = (i >> 5) / BGK;
            int col  = (n8_start + ni) * 8 + (lane >> 2);
            int k2   = (BGK0 + kcg) * 16 + 2 * (lane & 3);
            uint2 bv;
            bv.x = pack_bf16(Wk[(size_t)k2 * k4U + col],
                             Wk[(size_t)(k2 + 1) * k4U + col]);
            bv.y = pack_bf16(Wk[(size_t)(k2 + 8) * k4U + col],
                             Wk[(size_t)(k2 + 9) * k4U + col]);
            Bs[(ni * BGK + kcg) * 32 + lane] = bv;
        }
        __syncthreads();

        const int mt = wid & 3, half = wid >> 2;
        const int nloc  = half ? (n8_cnt - 13) : ((n8_cnt < 13) ? n8_cnt : 13);
        const int nbase = half ? 13 : 0;
        const int row   = mt * 16 + (lid >> 2);
        const int c2    = 2 * (lid & 3);

        for (int t = 0; t < kT; t++) {
            float acc[13][4];
#pragma unroll
            for (int i = 0; i < 13; i++)
#pragma unroll
                for (int k = 0; k < 4; k++) acc[i][k] = 0.f;

            const uint4* Ap = g_xf + (size_t)t * 4096 + BGK0 * 128 + mt * 32 + lid;
            uint4 a0 = __ldcg(Ap);
#pragma unroll
            for (int kcg = 0; kcg < BGK; kcg++) {
                uint4 a = a0;
                if (kcg < BGK - 1) a0 = __ldcg(Ap + (kcg + 1) * 128);
#pragma unroll
                for (int i = 0; i < 13; i++) {
                    if (i < nloc) {
                        uint2 b = Bs[((nbase + i) * BGK + kcg) * 32 + lid];
                        mma_bf16(acc[i], a.x, a.y, a.z, a.w, b.x, b.y);
                    }
                }
            }
#pragma unroll
            for (int i = 0; i < 13; i++) {
                if (i < nloc) {
                    size_t base = (((size_t)t * 512 + n8_start + nbase + i) * 64
                                   + row) * 8 + c2;
                    *(float2*)(g_xz2 + base)      = make_float2(acc[i][0], acc[i][1]);
                    *(float2*)(g_xz2 + base + 64) = make_float2(acc[i][2], acc[i][3]);
                }
            }
            __threadfence();
            __syncthreads();
            if (tid == 0) atomicAdd(&g_bgcnt[j * 32], 1u);
        }
        return;
    }

    // ================= FUSED LSTM CTA =================
    uint32_t*      Wr_f  = fsm + OFF_WRF;
    uint2*         Wk_f  = (uint2*)(fsm + OFF_WKF);
    float*         ring  = (float*)(fsm + OFF_RING);     // [4][64][34]
    float*         bia_s = (float*)(fsm + OFF_BIAS);
    volatile int*  pflag = (volatile int*)(fsm + OFF_FLAGS);      // [4]
    volatile int*  cflag = (volatile int*)(fsm + OFF_FLAGS + 4);  // [4]

    const int cta    = blockIdx.x;
    const int u_base = cta * 8;
    const int my_group = cta >> 4;

    // ---- cooperative init ----
    for (int i = 0; i < 64; i++) {           // Wr fragments (16384 u32)
        int lin = tid + i * NTHR;
        int reg = lin & 1;
        int ll  = (lin >> 1) & 31;
        int kcg = (lin >> 6) & 63;
        int q   = (lin >> 12) & 3;
        int lg = ll >> 2, lq = ll & 3;
        int k  = kcg * 16 + 2 * lq + 8 * reg;
        int col = q * kU + u_base + lg;
        float v0 = Wr[(size_t)k * k4U + col];
        float v1 = Wr[(size_t)(k + 1) * k4U + col];
        Wr_f[((q * 64 + kcg) * 32 + ll) * 2 + reg] = pack_bf16(v0, v1);
    }
    for (int i = 0; i < KHG * 4 * 32 / NTHR; i++) {   // Wk frags (kcg<24)
        int lin = tid + i * NTHR;
        int lane = lin & 31;
        int nt   = (lin >> 5) & 3;
        int kcg  = lin >> 7;
        int gcol = nt * kU + u_base + (lane >> 2);
        int k2   = kcg * 16 + 2 * (lane & 3);
        uint2 bv;
        bv.x = pack_bf16(Wk[(size_t)k2 * k4U + gcol],
                         Wk[(size_t)(k2 + 1) * k4U + gcol]);
        bv.y = pack_bf16(Wk[(size_t)(k2 + 8) * k4U + gcol],
                         Wk[(size_t)(k2 + 9) * k4U + gcol]);
        Wk_f[(kcg * 4 + nt) * 32 + lane] = bv;
    }
    if (tid < 32) bia_s[tid] = bias[(tid >> 3) * kU + u_base + (tid & 7)];
    if (tid < 4) { pflag[tid] = 0; cflag[tid] = 0; }
    __syncthreads();

    if (wid >= 4) {
        // ============ PRODUCER (warps 4-7): xz kcg<24 ============
        const int pw = wid - 4;
        const int r  = pw * 16 + (lid >> 2);
        const int cl = 2 * (lid & 3);
        for (int tp = 0; tp < kT; tp++) {
            const int s = tp & 3;
            if (tp >= 4) {
                int sp = 0;
                while (cflag[s] < tp - 3) { if (++sp > 4) __nanosleep(40); }
                __threadfence_block();
            }
            float cacc[4][4];
#pragma unroll
            for (int nt = 0; nt < 4; nt++)
#pragma unroll
                for (int k = 0; k < 4; k++) cacc[nt][k] = 0.f;

            const uint4* Ap = g_xf + (size_t)tp * 4096 + pw * 32 + lid;
            uint4 pbuf[4];
#pragma unroll
            for (int i = 0; i < 4; i++) pbuf[i] = __ldcg(Ap + i * 128);
#pragma unroll
            for (int kcg = 0; kcg < KHG; kcg++) {
                uint4 a = pbuf[kcg & 3];
                if (kcg < KHG - 4) pbuf[kcg & 3] = __ldcg(Ap + (kcg + 4) * 128);
#pragma unroll
                for (int nt = 0; nt < 4; nt++) {
                    uint2 bv = Wk_f[(kcg * 4 + nt) * 32 + lid];
                    mma_bf16(cacc[nt], a.x, a.y, a.z, a.w, bv.x, bv.y);
                }
            }
            float* rs = ring + (size_t)s * 64 * 34;
#pragma unroll
            for (int nt = 0; nt < 4; nt++) {
                int col = nt * 8 + cl;
                float bx = bia_s[col], by = bia_s[col + 1];
                float2 lo = make_float2(cacc[nt][0] + bx, cacc[nt][1] + by);
                float2 hi = make_float2(cacc[nt][2] + bx, cacc[nt][3] + by);
                *(float2*)&rs[(r)     * 34 + col] = lo;
                *(float2*)&rs[(r + 8) * 34 + col] = hi;
            }
            __threadfence_block();
            bar_named(3, 128);
            if (tid == 128) pflag[s] = tp + 1;
        }
    } else {
        // ============ CONSUMER (warps 0-3) ============
        const int w = wid, l = lid;
        const int grp = l >> 2, qd = l & 3;
        const int b0 = w * 16 + grp;
        const int j0 = 2 * qd;
        const int kcg_w = cta >> 1;
        const int hi_w  = cta & 1;

        int myj = 0;
        if (l < 4) myj = (128 * l + cta) / 26;   // owning bg CTA of n8 tile

        float cst[4] = {0.f, 0.f, 0.f, 0.f};

        for (int t = 0; t < kT; t++) {
            const uint4* Ag = (const uint4*)(g_h + (size_t)(t & 1) * 32768);
            uint32_t*  hwrt = g_h + (size_t)((t + 1) & 1) * 32768;

            // bg partial ready?  (lanes 0-3 poll; bg has 40% slack -> instant)
            {
                int sp = 0;
                for (;;) {
                    unsigned ok = 1u;
                    if (l < 4) ok = (ld_acq(&g_bgcnt[myj * 32]) >= (unsigned)(t + 1));
                    if (__ballot_sync(0xffffffffu, ok != 0u) == 0xffffffffu) break;
                    if (++sp > 4) __nanosleep(40);
                }
            }
            float2 pz[8];
#pragma unroll
            for (int q = 0; q < 4; q++) {
                size_t nb = ((size_t)t * 512 + 128 * q + cta) * 64;
                pz[2 * q]     = __ldcg((const float2*)(g_xz2 + (nb + b0) * 8 + j0));
                pz[2 * q + 1] = __ldcg((const float2*)(g_xz2 + (nb + b0 + 8) * 8 + j0));
            }

            unsigned tgt = 16u * (unsigned)t;
            unsigned rdy = (t == 0) ? 0xffffffffu : 0u;
            const int g0 = my_group;
            {
                int sp = 0;
                while (!((rdy >> g0) & 1u)) {
                    rdy = poll_groups(l, tgt, rdy);
                    if (!((rdy >> g0) & 1u) && ++sp > 4) __nanosleep(40);
                }
            }

            float acc[4][2][4];
#pragma unroll
            for (int q = 0; q < 4; q++)
#pragma unroll
                for (int p = 0; p < 2; p++)
#pragma unroll
                    for (int k = 0; k < 4; k++) acc[q][p][k] = 0.f;

            uint4 abuf[8];
#pragma unroll
            for (int i = 0; i < 8; i++)
                abuf[i] = __ldcg(Ag + (8 * g0 + i) * 128 + tid);

            for (int ch = 0; ch < 8; ch++) {
                const int g  = (ch + my_group) & 7;
                const int gn = (g + 1) & 7;
                if (ch < 7) {
                    int sp = 0;
                    while (!((rdy >> gn) & 1u)) {
                        rdy = poll_groups(l, tgt, rdy);
                        if (!((rdy >> gn) & 1u) && ++sp > 4) __nanosleep(40);
                    }
                }
#pragma unroll
                for (int k8 = 0; k8 < 8; k8++) {
                    uint4 a = abuf[k8];
                    if (ch < 7) abuf[k8] = __ldcg(Ag + (8 * gn + k8) * 128 + tid);
                    int kcg = 8 * g + k8;
#pragma unroll
                    for (int q = 0; q < 4; q++) {
                        uint2 bv = *(const uint2*)&Wr_f[((q * 64 + kcg) * 32 + l) * 2];
                        mma_bf16(acc[q][k8 & 1], a.x, a.y, a.z, a.w, bv.x, bv.y);
                    }
                }
            }

            const int s = t & 3;
            {
                int sp = 0;
                while (pflag[s] < t + 1) { if (++sp > 4) __nanosleep(40); }
            }
            __threadfence_block();
            const float* rs = ring + (size_t)s * 64 * 34;
            float2 xz[2][4];
#pragma unroll
            for (int r2 = 0; r2 < 2; r2++)
#pragma unroll
                for (int q = 0; q < 4; q++)
                    xz[r2][q] = *(const float2*)&rs[(b0 + 8 * r2) * 34 + q * 8 + j0];

#pragma unroll
            for (int r2 = 0; r2 < 2; r2++) {
                float hv[2];
#pragma unroll
                for (int d = 0; d < 2; d++) {
                    int idx = 2 * r2 + d;
                    float zi = acc[0][0][idx] + acc[0][1][idx]
                             + (d ? xz[r2][0].y : xz[r2][0].x)
                             + (d ? pz[0 + r2].y : pz[0 + r2].x);
                    float zf = acc[1][0][idx] + acc[1][1][idx]
                             + (d ? xz[r2][1].y : xz[r2][1].x)
                             + (d ? pz[2 + r2].y : pz[2 + r2].x);
                    float zg = acc[2][0][idx] + acc[2][1][idx]
                             + (d ? xz[r2][2].y : xz[r2][2].x)
                             + (d ? pz[4 + r2].y : pz[4 + r2].x);
                    float zo = acc[3][0][idx] + acc[3][1][idx]
                             + (d ? xz[r2][3].y : xz[r2][3].x)
                             + (d ? pz[6 + r2].y : pz[6 + r2].x);
                    float ig = sigmoid_fast(zi);
                    float fg = sigmoid_fast(zf);
                    float gg = tanh_fast(zg);
                    float og = sigmoid_fast(zo);
                    float cv = fg * cst[idx] + ig * gg;
                    cst[idx] = cv;
                    hv[d] = og * tanh_fast(cv);
                }
                hwrt[(kcg_w * 128 + tid) * 4 + 2 * hi_w + r2] = pack_bf16(hv[0], hv[1]);
            }

            __threadfence();
            bar_named(2, 128);
            if (tid == 0) {
                atomicAdd(&g_cnt[my_group * 32], 1u);
                cflag[s] = t + 1;
            }
        }
    }
}

// ---------------------------------------------------------------------------
// Kernel 3a: logits partials. grid (4 kchunks, 64 rows); k-chunk = 256.
// ---------------------------------------------------------------------------
__device__ __forceinline__ float h_read_b0(int b, int u) {
    uint32_t v = g_h[((u >> 4) * 128 + (b >> 4) * 32 + (b & 7) * 4 + ((u & 7) >> 1)) * 4
                     + 2 * ((u >> 3) & 1) + ((b >> 3) & 1)];
    return __uint_as_float((u & 1) ? (v & 0xffff0000u) : (v << 16));
}

__global__ __launch_bounds__(256) void logits_part(const float* __restrict__ Wd) {
    __shared__ float hk_s[256];
    const int kc  = blockIdx.x;
    const int b   = blockIdx.y;
    const int tid = threadIdx.x;
    const int k0  = kc * 256;
    hk_s[tid] = h_read_b0(b, k0 + tid);
    __syncthreads();

    if (tid < 250) {
        const int j0 = tid * 4;
        float acc[4] = {0.f, 0.f, 0.f, 0.f};
        const float* wp = Wd + (size_t)k0 * kC + j0;
#pragma unroll 8
        for (int k = 0; k < 256; k++) {
            float4 wv = *(const float4*)(wp + (size_t)k * kC);
            float  hk = hk_s[k];
            acc[0] = fmaf(hk, wv.x, acc[0]);
            acc[1] = fmaf(hk, wv.y, acc[1]);
            acc[2] = fmaf(hk, wv.z, acc[2]);
            acc[3] = fmaf(hk, wv.w, acc[3]);
        }
        *(float4*)&g_lpart[((size_t)kc * 64 + b) * kC + j0] =
            make_float4(acc[0], acc[1], acc[2], acc[3]);
    }
}

// ---------------------------------------------------------------------------
// Kernel 3b: softmax over summed partials (fixed-order, deterministic)
// ---------------------------------------------------------------------------
__global__ __launch_bounds__(256) void softmax_final(
    const float* __restrict__ bd, float* __restrict__ out) {
    __shared__ float red[256];
    const int b   = blockIdx.x;
    const int tid = threadIdx.x;
    const int j0  = tid * 4;
    const bool active = (j0 < kC);

    float acc[4] = {0.f, 0.f, 0.f, 0.f};
    if (active) {
#pragma unroll
        for (int p = 0; p < 4; p++) {
            float4 v = *(const float4*)&g_lpart[((size_t)p * 64 + b) * kC + j0];
            acc[0] += v.x; acc[1] += v.y; acc[2] += v.z; acc[3] += v.w;
        }
        float4 bv = *(const float4*)&bd[j0];
        acc[0] += bv.x; acc[1] += bv.y; acc[2] += bv.z; acc[3] += bv.w;
    }

    float m = active ? fmaxf(fmaxf(acc[0], acc[1]), fmaxf(acc[2], acc[3]))
                     : -INFINITY;
    red[tid] = m;
    __syncthreads();
    for (int s = 128; s > 0; s >>= 1) {
        if (tid < s) red[tid] = fmaxf(red[tid], red[tid + s]);
        __syncthreads();
    }
    float mx = red[0];
    __syncthreads();

    float e[4] = {0.f, 0.f, 0.f, 0.f};
    float psum = 0.f;
    if (active) {
#pragma unroll
        for (int cc = 0; cc < 4; cc++) { e[cc] = expf(acc[cc] - mx); psum += e[cc]; }
    }
    red[tid] = psum;
    __syncthreads();
    for (int s = 128; s > 0; s >>= 1) {
        if (tid < s) red[tid] += red[tid + s];
        __syncthreads();
    }
    float inv = 1.f / red[0];
    if (active) {
#pragma unroll
        for (int cc = 0; cc < 4; cc++) out[(size_t)b * kC + j0 + cc] = e[cc] * inv;
    }
}

// ---------------------------------------------------------------------------
// Launch
// ---------------------------------------------------------------------------
extern "C" void kernel_launch(void* const* d_in, const int* in_sizes, int n_in,
                              void* d_out, int out_size) {
    const float* x    = (const float*)d_in[0];
    const float* Wk   = (const float*)d_in[1];
    const float* Wr   = (const float*)d_in[2];
    const float* bias = (const float*)d_in[3];
    const float* Wd   = (const float*)d_in[4];
    const float* bd   = (const float*)d_in[5];
    float* out = (float*)d_out;

    const int smem_bytes = SMEM_U32 * (int)sizeof(uint32_t);   // 125088
    cudaFuncSetAttribute(lstm_fused, cudaFuncAttributeMaxDynamicSharedMemorySize,
                         smem_bytes);

    reset_kernel<<<64, 256>>>();
    permute_x<<<(int)((size_t)kT * 4096 / 256), 256>>>(x);
    lstm_fused<<<NCTA, NTHR, smem_bytes>>>(Wr, Wk, bias);
    logits_part<<<dim3(4, 64), 256>>>(Wd);
    softmax_final<<<kB, 256>>>(bd, out);
}

// round 13
// speedup vs baseline: 1.0174x; 1.0174x over previous
#include <cuda_runtime.h>
#include <cuda_bf16.h>
#include <math.h>
#include <stdint.h>

// Problem constants
static constexpr int kB  = 64;      // batch
static constexpr int kT  = 1024;    // time steps
static constexpr int kF  = 512;     // input features
static constexpr int kU  = 1024;    // hidden units
static constexpr int k4U = 4096;    // 4*U
static constexpr int kC  = 1000;    // classes

static constexpr int NCTA = 128;    // persistent CTAs (1/SM)
static constexpr int NTHR = 256;    // 8 warps: 0-3 consumers (LSTM), 4-7 producers (xz)

// SMEM layout (u32 units within dynamic smem)
static constexpr int OFF_WRF   = 0;        // Wr fragments: 16384 u32 (64 KB)
static constexpr int OFF_WKF   = 16384;    // Wk fragments: 4096 uint2 = 8192 u32 (32 KB)
static constexpr int OFF_RING  = 24576;    // xz ring: 4 stages x 64 x 34 fp32 = 8704 u32
static constexpr int OFF_BIAS  = 33280;    // 32 fp32
static constexpr int OFF_FLAGS = 33312;    // pflag[4], lcnt
static constexpr int SMEM_U32  = 33320;    // 133280 bytes

// Scratch (device globals: allocation-free per harness rules)
// x permuted to bf16 A-fragment order: idx(t,kcg,mt,lane) = t*4096 + kcg*128 + mt*32 + lane
__device__ uint4    g_xf[(size_t)kT * 4096];       // 67 MB
// h ping-pong, bf16, permuted into m16n8k16 A-fragment order (see R5 comment)
__device__ uint32_t g_h[2 * 32768];
// Per-group monotonic warp-arrival counters. Group g = CTAs [16g,16g+16);
// 64 warp-arrivals per group per step.
__device__ unsigned g_cnt[8 * 32];
// logits partials
__device__ float    g_lpart[4 * 64 * kC];

__device__ __forceinline__ uint32_t pack_bf16(float lo, float hi) {
    uint32_t r;
    asm("cvt.rn.bf16x2.f32 %0, %1, %2;" : "=r"(r) : "f"(hi), "f"(lo));
    return r;
}
__device__ __forceinline__ float tanh_fast(float x) {
    float r;
    asm("tanh.approx.f32 %0, %1;" : "=f"(r) : "f"(x));
    return r;
}
__device__ __forceinline__ float sigmoid_fast(float x) {
    return 1.f / (1.f + __expf(-x));
}
__device__ __forceinline__ void mma_bf16(float c[4], uint32_t a0, uint32_t a1,
                                         uint32_t a2, uint32_t a3,
                                         uint32_t b0, uint32_t b1) {
    asm volatile(
        "mma.sync.aligned.m16n8k16.row.col.f32.bf16.bf16.f32 "
        "{%0,%1,%2,%3},{%4,%5,%6,%7},{%8,%9},{%0,%1,%2,%3};"
        : "+f"(c[0]), "+f"(c[1]), "+f"(c[2]), "+f"(c[3])
        : "r"(a0), "r"(a1), "r"(a2), "r"(a3), "r"(b0), "r"(b1));
}
__device__ __forceinline__ void bar_named(int id, int cnt) {
    asm volatile("bar.sync %0, %1;" :: "r"(id), "r"(cnt) : "memory");
}
__device__ __forceinline__ unsigned ld_acq(const unsigned* p) {
    unsigned v;
    asm volatile("ld.acquire.gpu.u32 %0, [%1];" : "=r"(v) : "l"(p) : "memory");
    return v;
}
// Warp-cooperative group-counter poll. Lanes 0-7 own one group counter each.
__device__ __forceinline__ unsigned poll_groups(int lane, unsigned tgt,
                                                unsigned rdy) {
    unsigned ok = 1u;
    if (lane < 8 && !((rdy >> lane) & 1u)) {
        unsigned v = ld_acq(&g_cnt[lane * 32]);
        ok = (v >= tgt) ? 1u : 0u;
    }
    return __ballot_sync(0xffffffffu, ok != 0u);
}

// ---------------------------------------------------------------------------
// Kernel 0: reset state so every graph replay is deterministic
// ---------------------------------------------------------------------------
__global__ void reset_kernel() {
    int idx = blockIdx.x * blockDim.x + threadIdx.x;
    if (idx < 8 * 32) g_cnt[idx] = 0u;
    for (int i = idx; i < 2 * 32768; i += gridDim.x * blockDim.x) g_h[i] = 0u;
}

// ---------------------------------------------------------------------------
// Kernel 1: permute x -> bf16 A-fragment order (one uint4 per thread)
// ---------------------------------------------------------------------------
__global__ __launch_bounds__(256) void permute_x(const float* __restrict__ x) {
    size_t idx = (size_t)blockIdx.x * 256 + threadIdx.x;   // < kT*4096
    int lane = idx & 31;
    int mt   = (idx >> 5) & 3;
    int kcg  = (idx >> 7) & 31;
    int t    = (int)(idx >> 12);
    int r  = mt * 16 + (lane >> 2);                        // batch row
    int k2 = kcg * 16 + 2 * (lane & 3);
    const float* x0 = x + ((size_t)r * kT + t) * kF;
    const float* x8 = x + ((size_t)(r + 8) * kT + t) * kF;
    float2 v00 = *(const float2*)(x0 + k2);
    float2 v10 = *(const float2*)(x8 + k2);
    float2 v01 = *(const float2*)(x0 + k2 + 8);
    float2 v11 = *(const float2*)(x8 + k2 + 8);
    uint4 o;
    o.x = pack_bf16(v00.x, v00.y);
    o.y = pack_bf16(v10.x, v10.y);
    o.z = pack_bf16(v01.x, v01.y);
    o.w = pack_bf16(v11.x, v11.y);
    g_xf[idx] = o;
}

// ---------------------------------------------------------------------------
// Kernel 2: fused persistent LSTM (R8 structure, warp-granular publish).
// Warps 0-3: recurrence mma + gates; warps 4-7: per-step xz (full K=512)
// into a 4-deep SMEM ring. No consumer-side block barrier: each consumer
// warp publishes its own arrival (group target 64/step) and a SMEM ring
// credit; producers gate ring reuse on the credit counter.
// ---------------------------------------------------------------------------
extern __shared__ uint32_t fsm[];

__global__ __launch_bounds__(NTHR, 1) void lstm_fused(
    const float* __restrict__ Wr, const float* __restrict__ Wk,
    const float* __restrict__ bias) {
    uint32_t*      Wr_f  = fsm + OFF_WRF;
    uint2*         Wk_f  = (uint2*)(fsm + OFF_WKF);
    float*         ring  = (float*)(fsm + OFF_RING);     // [4][64][34]
    float*         bia_s = (float*)(fsm + OFF_BIAS);
    volatile int*  pflag = (volatile int*)(fsm + OFF_FLAGS);      // [4]
    int*           lcnt  = (int*)(fsm + OFF_FLAGS + 4);           // ring credits

    const int tid = threadIdx.x;
    const int wid = tid >> 5, lid = tid & 31;
    const int u_base = blockIdx.x * 8;
    const int my_group = blockIdx.x >> 4;

    // ---- cooperative init (all 8 warps) ----
    // Wr fragments (16384 u32)
    for (int i = 0; i < 64; i++) {
        int lin = tid + i * NTHR;
        int reg = lin & 1;
        int ll  = (lin >> 1) & 31;
        int kcg = (lin >> 6) & 63;
        int q   = (lin >> 12) & 3;
        int lg = ll >> 2, lq = ll & 3;
        int k  = kcg * 16 + 2 * lq + 8 * reg;
        int col = q * kU + u_base + lg;
        float v0 = Wr[(size_t)k * k4U + col];
        float v1 = Wr[(size_t)(k + 1) * k4U + col];
        Wr_f[((q * 64 + kcg) * 32 + ll) * 2 + reg] = pack_bf16(v0, v1);
    }
    // Wk fragments (4096 uint2): all 32 kcg
    for (int i = 0; i < 16; i++) {
        int lin = tid + i * NTHR;
        int lane = lin & 31;
        int nt   = (lin >> 5) & 3;
        int kcg  = lin >> 7;
        int gcol = nt * kU + u_base + (lane >> 2);
        int k2   = kcg * 16 + 2 * (lane & 3);
        uint2 bv;
        bv.x = pack_bf16(Wk[(size_t)k2 * k4U + gcol],
                         Wk[(size_t)(k2 + 1) * k4U + gcol]);
        bv.y = pack_bf16(Wk[(size_t)(k2 + 8) * k4U + gcol],
                         Wk[(size_t)(k2 + 9) * k4U + gcol]);
        Wk_f[(kcg * 4 + nt) * 32 + lane] = bv;
    }
    if (tid < 32) bia_s[tid] = bias[(tid >> 3) * kU + u_base + (tid & 7)];
    if (tid < 4) pflag[tid] = 0;
    if (tid == 0) *lcnt = 0;
    __syncthreads();

    if (wid >= 4) {
        // ================= PRODUCER (warps 4-7): xz full K =================
        const int pw = wid - 4;              // M-subtile (16 batch rows)
        const int r  = pw * 16 + (lid >> 2);
        const int cl = 2 * (lid & 3);
        for (int tp = 0; tp < kT; tp++) {
            const int s = tp & 3;
            if (tp >= 4) {
                // ring credit: all 4 consumer warps done with step tp-4
                int sp = 0;
                int tgt = 4 * (tp - 3);
                while (*(volatile int*)lcnt < tgt) {
                    if (++sp > 4) __nanosleep(40);
                }
                __threadfence_block();
            }
            float cacc[4][4];
#pragma unroll
            for (int nt = 0; nt < 4; nt++)
#pragma unroll
                for (int k = 0; k < 4; k++) cacc[nt][k] = 0.f;

            const uint4* Ap = g_xf + (size_t)tp * 4096 + pw * 32 + lid;
            uint4 pbuf[4];
#pragma unroll
            for (int i = 0; i < 4; i++) pbuf[i] = __ldcg(Ap + i * 128);
#pragma unroll 4
            for (int kcg = 0; kcg < 32; kcg++) {
                uint4 a = pbuf[kcg & 3];
                if (kcg < 28) pbuf[kcg & 3] = __ldcg(Ap + (kcg + 4) * 128);
#pragma unroll
                for (int nt = 0; nt < 4; nt++) {
                    uint2 bv = Wk_f[(kcg * 4 + nt) * 32 + lid];
                    mma_bf16(cacc[nt], a.x, a.y, a.z, a.w, bv.x, bv.y);
                }
            }
            // epilogue: bias + ring store
            float* rs = ring + (size_t)s * 64 * 34;
#pragma unroll
            for (int nt = 0; nt < 4; nt++) {
                int col = nt * 8 + cl;
                float bx = bia_s[col], by = bia_s[col + 1];
                float2 lo = make_float2(cacc[nt][0] + bx, cacc[nt][1] + by);
                float2 hi = make_float2(cacc[nt][2] + bx, cacc[nt][3] + by);
                *(float2*)&rs[(r)     * 34 + col] = lo;
                *(float2*)&rs[(r + 8) * 34 + col] = hi;
            }
            __threadfence_block();
            bar_named(3, 128);               // producer warps only
            if (tid == 128) pflag[s] = tp + 1;
        }
    } else {
        // ================= CONSUMER (warps 0-3) =================
        const int w = wid, l = lid;
        const int grp = l >> 2, qd = l & 3;
        const int b0 = w * 16 + grp;         // batch rows b0, b0+8
        const int j0 = 2 * qd;               // units j0, j0+1
        const int kcg_w = blockIdx.x >> 1;
        const int hi_w  = blockIdx.x & 1;

        float cst[4] = {0.f, 0.f, 0.f, 0.f};

        for (int t = 0; t < kT; t++) {
            const uint4* Ag = (const uint4*)(g_h + (size_t)(t & 1) * 32768);
            uint32_t*  hwrt = g_h + (size_t)((t + 1) & 1) * 32768;

            // Group-ready mask: warp-arrival counters, 64 per group per step.
            unsigned tgt = 64u * (unsigned)t;
            unsigned rdy = (t == 0) ? 0xffffffffu : 0u;
            const int g0 = my_group;
            {
                int sp = 0;
                while (!((rdy >> g0) & 1u)) {
                    rdy = poll_groups(l, tgt, rdy);
                    if (!((rdy >> g0) & 1u) && ++sp > 4) __nanosleep(40);
                }
            }

            float acc[4][2][4];
#pragma unroll
            for (int q = 0; q < 4; q++)
#pragma unroll
                for (int p = 0; p < 2; p++)
#pragma unroll
                    for (int k = 0; k < 4; k++) acc[q][p][k] = 0.f;

            uint4 abuf[8];
#pragma unroll
            for (int i = 0; i < 8; i++)
                abuf[i] = __ldcg(Ag + (8 * g0 + i) * 128 + tid);

            for (int ch = 0; ch < 8; ch++) {
                const int g  = (ch + my_group) & 7;
                const int gn = (g + 1) & 7;
                if (ch < 7) {
                    int sp = 0;
                    while (!((rdy >> gn) & 1u)) {
                        rdy = poll_groups(l, tgt, rdy);
                        if (!((rdy >> gn) & 1u) && ++sp > 4) __nanosleep(40);
                    }
                }
#pragma unroll
                for (int k8 = 0; k8 < 8; k8++) {
                    uint4 a = abuf[k8];
                    if (ch < 7) abuf[k8] = __ldcg(Ag + (8 * gn + k8) * 128 + tid);
                    int kcg = 8 * g + k8;
#pragma unroll
                    for (int q = 0; q < 4; q++) {
                        uint2 bv = *(const uint2*)&Wr_f[((q * 64 + kcg) * 32 + l) * 2];
                        mma_bf16(acc[q][k8 & 1], a.x, a.y, a.z, a.w, bv.x, bv.y);
                    }
                }
            }

            // xz from SMEM ring
            const int s = t & 3;
            {
                int sp = 0;
                while (pflag[s] < t + 1) { if (++sp > 4) __nanosleep(40); }
            }
            __threadfence_block();
            const float* rs = ring + (size_t)s * 64 * 34;
            float2 xz[2][4];
#pragma unroll
            for (int r2 = 0; r2 < 2; r2++)
#pragma unroll
                for (int q = 0; q < 4; q++)
                    xz[r2][q] = *(const float2*)&rs[(b0 + 8 * r2) * 34 + q * 8 + j0];

            // gate phase (registers only)
#pragma unroll
            for (int r2 = 0; r2 < 2; r2++) {
                float hv[2];
#pragma unroll
                for (int d = 0; d < 2; d++) {
                    int idx = 2 * r2 + d;
                    float zi = acc[0][0][idx] + acc[0][1][idx] + (d ? xz[r2][0].y : xz[r2][0].x);
                    float zf = acc[1][0][idx] + acc[1][1][idx] + (d ? xz[r2][1].y : xz[r2][1].x);
                    float zg = acc[2][0][idx] + acc[2][1][idx] + (d ? xz[r2][2].y : xz[r2][2].x);
                    float zo = acc[3][0][idx] + acc[3][1][idx] + (d ? xz[r2][3].y : xz[r2][3].x);
                    float ig = sigmoid_fast(zi);
                    float fg = sigmoid_fast(zf);
                    float gg = tanh_fast(zg);
                    float og = sigmoid_fast(zo);
                    float cv = fg * cst[idx] + ig * gg;
                    cst[idx] = cv;
                    hv[d] = og * tanh_fast(cv);
                }
                hwrt[(kcg_w * 128 + tid) * 4 + 2 * hi_w + r2] = pack_bf16(hv[0], hv[1]);
            }

            // warp-granular publish: h arrival (cross-CTA) + ring credit (CTA)
            __threadfence();
            __syncwarp();
            if (l == 0) {
                atomicAdd(&g_cnt[my_group * 32], 1u);
                atomicAdd_block(lcnt, 1);
            }
        }
    }
}

// ---------------------------------------------------------------------------
// Kernel 3a: logits partials. grid (4 kchunks, 64 rows); k-chunk = 256.
// ---------------------------------------------------------------------------
__device__ __forceinline__ float h_read_b0(int b, int u) {
    uint32_t v = g_h[((u >> 4) * 128 + (b >> 4) * 32 + (b & 7) * 4 + ((u & 7) >> 1)) * 4
                     + 2 * ((u >> 3) & 1) + ((b >> 3) & 1)];
    return __uint_as_float((u & 1) ? (v & 0xffff0000u) : (v << 16));
}

__global__ __launch_bounds__(256) void logits_part(const float* __restrict__ Wd) {
    __shared__ float hk_s[256];
    const int kc  = blockIdx.x;
    const int b   = blockIdx.y;
    const int tid = threadIdx.x;
    const int k0  = kc * 256;
    hk_s[tid] = h_read_b0(b, k0 + tid);
    __syncthreads();

    if (tid < 250) {
        const int j0 = tid * 4;
        float acc[4] = {0.f, 0.f, 0.f, 0.f};
        const float* wp = Wd + (size_t)k0 * kC + j0;
#pragma unroll 8
        for (int k = 0; k < 256; k++) {
            float4 wv = *(const float4*)(wp + (size_t)k * kC);
            float  hk = hk_s[k];
            acc[0] = fmaf(hk, wv.x, acc[0]);
            acc[1] = fmaf(hk, wv.y, acc[1]);
            acc[2] = fmaf(hk, wv.z, acc[2]);
            acc[3] = fmaf(hk, wv.w, acc[3]);
        }
        *(float4*)&g_lpart[((size_t)kc * 64 + b) * kC + j0] =
            make_float4(acc[0], acc[1], acc[2], acc[3]);
    }
}

// ---------------------------------------------------------------------------
// Kernel 3b: softmax over summed partials (fixed-order, deterministic)
// ---------------------------------------------------------------------------
__global__ __launch_bounds__(256) void softmax_final(
    const float* __restrict__ bd, float* __restrict__ out) {
    __shared__ float red[256];
    const int b   = blockIdx.x;
    const int tid = threadIdx.x;
    const int j0  = tid * 4;
    const bool active = (j0 < kC);

    float acc[4] = {0.f, 0.f, 0.f, 0.f};
    if (active) {
#pragma unroll
        for (int p = 0; p < 4; p++) {
            float4 v = *(const float4*)&g_lpart[((size_t)p * 64 + b) * kC + j0];
            acc[0] += v.x; acc[1] += v.y; acc[2] += v.z; acc[3] += v.w;
        }
        float4 bv = *(const float4*)&bd[j0];
        acc[0] += bv.x; acc[1] += bv.y; acc[2] += bv.z; acc[3] += bv.w;
    }

    float m = active ? fmaxf(fmaxf(acc[0], acc[1]), fmaxf(acc[2], acc[3]))
                     : -INFINITY;
    red[tid] = m;
    __syncthreads();
    for (int s = 128; s > 0; s >>= 1) {
        if (tid < s) red[tid] = fmaxf(red[tid], red[tid + s]);
        __syncthreads();
    }
    float mx = red[0];
    __syncthreads();

    float e[4] = {0.f, 0.f, 0.f, 0.f};
    float psum = 0.f;
    if (active) {
#pragma unroll
        for (int cc = 0; cc < 4; cc++) { e[cc] = expf(acc[cc] - mx); psum += e[cc]; }
    }
    red[tid] = psum;
    __syncthreads();
    for (int s = 128; s > 0; s >>= 1) {
        if (tid < s) red[tid] += red[tid + s];
        __syncthreads();
    }
    float inv = 1.f / red[0];
    if (active) {
#pragma unroll
        for (int cc = 0; cc < 4; cc++) out[(size_t)b * kC + j0 + cc] = e[cc] * inv;
    }
}

// ---------------------------------------------------------------------------
// Launch
// ---------------------------------------------------------------------------
extern "C" void kernel_launch(void* const* d_in, const int* in_sizes, int n_in,
                              void* d_out, int out_size) {
    const float* x    = (const float*)d_in[0];
    const float* Wk   = (const float*)d_in[1];
    const float* Wr   = (const float*)d_in[2];
    const float* bias = (const float*)d_in[3];
    const float* Wd   = (const float*)d_in[4];
    const float* bd   = (const float*)d_in[5];
    float* out = (float*)d_out;

    const int smem_bytes = SMEM_U32 * (int)sizeof(uint32_t);   // 133280
    cudaFuncSetAttribute(lstm_fused, cudaFuncAttributeMaxDynamicSharedMemorySize,
                         smem_bytes);

    reset_kernel<<<64, 256>>>();
    permute_x<<<(int)((size_t)kT * 4096 / 256), 256>>>(x);
    lstm_fused<<<NCTA, NTHR, smem_bytes>>>(Wr, Wk, bias);
    logits_part<<<dim3(4, 64), 256>>>(Wd);
    softmax_final<<<kB, 256>>>(bd, out);
}

// round 15
// speedup vs baseline: 1.0206x; 1.0032x over previous
#include <cuda_runtime.h>
#include <cuda_fp16.h>
#include <math.h>
#include <stdint.h>

// Problem constants
static constexpr int kB  = 64;      // batch
static constexpr int kT  = 1024;    // time steps
static constexpr int kF  = 512;     // input features
static constexpr int kU  = 1024;    // hidden units
static constexpr int k4U = 4096;    // 4*U
static constexpr int kC  = 1000;    // classes

static constexpr int NCTA = 128;    // persistent CTAs (1/SM)
static constexpr int NTHR = 256;    // 8 warps: 0-3 consumers (LSTM), 4-7 producers (xz)

// SMEM layout (u32 units within dynamic smem)
static constexpr int OFF_WRF   = 0;        // Wr fp16 fragments: 16384 u32 (64 KB)
static constexpr int OFF_WKF   = 16384;    // Wk fp16 frags: 4096 uint2 = 8192 u32 (32 KB)
static constexpr int OFF_RING  = 24576;    // xz ring: 4 stages x 64 x 34 fp32 = 8704 u32
static constexpr int OFF_BIAS  = 33280;    // 32 fp32
static constexpr int OFF_FLAGS = 33312;    // pflag[4], lcnt
static constexpr int SMEM_U32  = 33320;    // 133280 bytes

// Scratch (device globals: allocation-free per harness rules)
// x permuted to fp16 A-fragment order: idx(t,kcg,mt,lane) = t*4096 + kcg*128 + mt*32 + lane
__device__ uint4    g_xf[(size_t)kT * 4096];       // 67 MB
// h ping-pong, fp16, permuted into m16n8k16 A-fragment order (see R5 comment)
__device__ uint32_t g_h[2 * 32768];
// Per-group monotonic warp-arrival counters (64 arrivals/group/step)
__device__ unsigned g_cnt[8 * 32];
// logits partials (8 k-chunks)
__device__ float    g_lpart[8 * 64 * kC];

__device__ __forceinline__ uint32_t pack_f16(float lo, float hi) {
    uint32_t r;
    asm("cvt.rn.f16x2.f32 %0, %1, %2;" : "=r"(r) : "f"(hi), "f"(lo));
    return r;
}
__device__ __forceinline__ float tanh_fast(float x) {
    float r;
    asm("tanh.approx.f32 %0, %1;" : "=f"(r) : "f"(x));
    return r;
}
__device__ __forceinline__ float sigmoid_fast(float x) {
    return 1.f / (1.f + __expf(-x));
}
__device__ __forceinline__ void mma_f16(float c[4], uint32_t a0, uint32_t a1,
                                        uint32_t a2, uint32_t a3,
                                        uint32_t b0, uint32_t b1) {
    asm volatile(
        "mma.sync.aligned.m16n8k16.row.col.f32.f16.f16.f32 "
        "{%0,%1,%2,%3},{%4,%5,%6,%7},{%8,%9},{%0,%1,%2,%3};"
        : "+f"(c[0]), "+f"(c[1]), "+f"(c[2]), "+f"(c[3])
        : "r"(a0), "r"(a1), "r"(a2), "r"(a3), "r"(b0), "r"(b1));
}
__device__ __forceinline__ void bar_named(int id, int cnt) {
    asm volatile("bar.sync %0, %1;" :: "r"(id), "r"(cnt) : "memory");
}
__device__ __forceinline__ unsigned ld_acq(const unsigned* p) {
    unsigned v;
    asm volatile("ld.acquire.gpu.u32 %0, [%1];" : "=r"(v) : "l"(p) : "memory");
    return v;
}
// Warp-cooperative group-counter poll. Lanes 0-7 own one group counter each.
__device__ __forceinline__ unsigned poll_groups(int lane, unsigned tgt,
                                                unsigned rdy) {
    unsigned ok = 1u;
    if (lane < 8 && !((rdy >> lane) & 1u)) {
        unsigned v = ld_acq(&g_cnt[lane * 32]);
        ok = (v >= tgt) ? 1u : 0u;
    }
    return __ballot_sync(0xffffffffu, ok != 0u);
}

// ---------------------------------------------------------------------------
// Kernel 0: reset (h buffer 0 only; buffer 1 is fully written before read)
// ---------------------------------------------------------------------------
__global__ void reset_kernel() {
    int idx = blockIdx.x * blockDim.x + threadIdx.x;
    if (idx < 8 * 32) g_cnt[idx] = 0u;
    for (int i = idx; i < 32768; i += gridDim.x * blockDim.x) g_h[i] = 0u;
}

// ---------------------------------------------------------------------------
// Kernel 1: permute x -> fp16 A-fragment order (one uint4 per thread)
// ---------------------------------------------------------------------------
__global__ __launch_bounds__(256) void permute_x(const float* __restrict__ x) {
    size_t idx = (size_t)blockIdx.x * 256 + threadIdx.x;   // < kT*4096
    int lane = idx & 31;
    int mt   = (idx >> 5) & 3;
    int kcg  = (idx >> 7) & 31;
    int t    = (int)(idx >> 12);
    int r  = mt * 16 + (lane >> 2);                        // batch row
    int k2 = kcg * 16 + 2 * (lane & 3);
    const float* x0 = x + ((size_t)r * kT + t) * kF;
    const float* x8 = x + ((size_t)(r + 8) * kT + t) * kF;
    float2 v00 = *(const float2*)(x0 + k2);
    float2 v10 = *(const float2*)(x8 + k2);
    float2 v01 = *(const float2*)(x0 + k2 + 8);
    float2 v11 = *(const float2*)(x8 + k2 + 8);
    uint4 o;
    o.x = pack_f16(v00.x, v00.y);
    o.y = pack_f16(v10.x, v10.y);
    o.z = pack_f16(v01.x, v01.y);
    o.w = pack_f16(v11.x, v11.y);
    g_xf[idx] = o;
}

// ---------------------------------------------------------------------------
// Kernel 2: fused persistent LSTM (R13 structure, fp16 operands).
// Warps 0-3: recurrence mma + gates; warps 4-7: per-step xz (full K=512)
// into a 4-deep SMEM ring. Warp-granular publish, JIT group polling.
// ---------------------------------------------------------------------------
extern __shared__ uint32_t fsm[];

__global__ __launch_bounds__(NTHR, 1) void lstm_fused(
    const float* __restrict__ Wr, const float* __restrict__ Wk,
    const float* __restrict__ bias) {
    uint32_t*      Wr_f  = fsm + OFF_WRF;
    uint2*         Wk_f  = (uint2*)(fsm + OFF_WKF);
    float*         ring  = (float*)(fsm + OFF_RING);     // [4][64][34]
    float*         bia_s = (float*)(fsm + OFF_BIAS);
    volatile int*  pflag = (volatile int*)(fsm + OFF_FLAGS);      // [4]
    int*           lcnt  = (int*)(fsm + OFF_FLAGS + 4);           // ring credits

    const int tid = threadIdx.x;
    const int wid = tid >> 5, lid = tid & 31;
    const int u_base = blockIdx.x * 8;
    const int my_group = blockIdx.x >> 4;

    // ---- cooperative init (all 8 warps) ----
    // Wr fp16 fragments (16384 u32)
    for (int i = 0; i < 64; i++) {
        int lin = tid + i * NTHR;
        int reg = lin & 1;
        int ll  = (lin >> 1) & 31;
        int kcg = (lin >> 6) & 63;
        int q   = (lin >> 12) & 3;
        int lg = ll >> 2, lq = ll & 3;
        int k  = kcg * 16 + 2 * lq + 8 * reg;
        int col = q * kU + u_base + lg;
        float v0 = Wr[(size_t)k * k4U + col];
        float v1 = Wr[(size_t)(k + 1) * k4U + col];
        Wr_f[((q * 64 + kcg) * 32 + ll) * 2 + reg] = pack_f16(v0, v1);
    }
    // Wk fp16 fragments (4096 uint2): all 32 kcg
    for (int i = 0; i < 16; i++) {
        int lin = tid + i * NTHR;
        int lane = lin & 31;
        int nt   = (lin >> 5) & 3;
        int kcg  = lin >> 7;
        int gcol = nt * kU + u_base + (lane >> 2);
        int k2   = kcg * 16 + 2 * (lane & 3);
        uint2 bv;
        bv.x = pack_f16(Wk[(size_t)k2 * k4U + gcol],
                        Wk[(size_t)(k2 + 1) * k4U + gcol]);
        bv.y = pack_f16(Wk[(size_t)(k2 + 8) * k4U + gcol],
                        Wk[(size_t)(k2 + 9) * k4U + gcol]);
        Wk_f[(kcg * 4 + nt) * 32 + lane] = bv;
    }
    if (tid < 32) bia_s[tid] = bias[(tid >> 3) * kU + u_base + (tid & 7)];
    if (tid < 4) pflag[tid] = 0;
    if (tid == 0) *lcnt = 0;
    __syncthreads();

    if (wid >= 4) {
        // ================= PRODUCER (warps 4-7): xz full K =================
        const int pw = wid - 4;              // M-subtile (16 batch rows)
        const int r  = pw * 16 + (lid >> 2);
        const int cl = 2 * (lid & 3);
        for (int tp = 0; tp < kT; tp++) {
            const int s = tp & 3;
            if (tp >= 4) {
                int sp = 0;
                int tgt = 4 * (tp - 3);
                while (*(volatile int*)lcnt < tgt) {
                    if (++sp > 4) __nanosleep(40);
                }
                __threadfence_block();
            }
            float cacc[4][4];
#pragma unroll
            for (int nt = 0; nt < 4; nt++)
#pragma unroll
                for (int k = 0; k < 4; k++) cacc[nt][k] = 0.f;

            const uint4* Ap = g_xf + (size_t)tp * 4096 + pw * 32 + lid;
            uint4 pbuf[4];
#pragma unroll
            for (int i = 0; i < 4; i++) pbuf[i] = __ldcg(Ap + i * 128);
#pragma unroll 4
            for (int kcg = 0; kcg < 32; kcg++) {
                uint4 a = pbuf[kcg & 3];
                if (kcg < 28) pbuf[kcg & 3] = __ldcg(Ap + (kcg + 4) * 128);
#pragma unroll
                for (int nt = 0; nt < 4; nt++) {
                    uint2 bv = Wk_f[(kcg * 4 + nt) * 32 + lid];
                    mma_f16(cacc[nt], a.x, a.y, a.z, a.w, bv.x, bv.y);
                }
            }
            // epilogue: bias + ring store
            float* rs = ring + (size_t)s * 64 * 34;
#pragma unroll
            for (int nt = 0; nt < 4; nt++) {
                int col = nt * 8 + cl;
                float bx = bia_s[col], by = bia_s[col + 1];
                float2 lo = make_float2(cacc[nt][0] + bx, cacc[nt][1] + by);
                float2 hi = make_float2(cacc[nt][2] + bx, cacc[nt][3] + by);
                *(float2*)&rs[(r)     * 34 + col] = lo;
                *(float2*)&rs[(r + 8) * 34 + col] = hi;
            }
            __threadfence_block();
            bar_named(3, 128);               // producer warps only
            if (tid == 128) pflag[s] = tp + 1;
        }
    } else {
        // ================= CONSUMER (warps 0-3) =================
        const int w = wid, l = lid;
        const int grp = l >> 2, qd = l & 3;
        const int b0 = w * 16 + grp;         // batch rows b0, b0+8
        const int j0 = 2 * qd;               // units j0, j0+1
        const int kcg_w = blockIdx.x >> 1;
        const int hi_w  = blockIdx.x & 1;

        float cst[4] = {0.f, 0.f, 0.f, 0.f};

        for (int t = 0; t < kT; t++) {
            const uint4* Ag = (const uint4*)(g_h + (size_t)(t & 1) * 32768);
            uint32_t*  hwrt = g_h + (size_t)((t + 1) & 1) * 32768;

            // Group-ready mask: warp-arrival counters, 64 per group per step.
            unsigned tgt = 64u * (unsigned)t;
            unsigned rdy = (t == 0) ? 0xffffffffu : 0u;
            const int g0 = my_group;
            {
                int sp = 0;
                while (!((rdy >> g0) & 1u)) {
                    rdy = poll_groups(l, tgt, rdy);
                    if (!((rdy >> g0) & 1u) && ++sp > 4) __nanosleep(40);
                }
            }

            float acc[4][2][4];
#pragma unroll
            for (int q = 0; q < 4; q++)
#pragma unroll
                for (int p = 0; p < 2; p++)
#pragma unroll
                    for (int k = 0; k < 4; k++) acc[q][p][k] = 0.f;

            uint4 abuf[8];
#pragma unroll
            for (int i = 0; i < 8; i++)
                abuf[i] = __ldcg(Ag + (8 * g0 + i) * 128 + tid);

            for (int ch = 0; ch < 8; ch++) {
                const int g  = (ch + my_group) & 7;
                const int gn = (g + 1) & 7;
                if (ch < 7) {
                    int sp = 0;
                    while (!((rdy >> gn) & 1u)) {
                        rdy = poll_groups(l, tgt, rdy);
                        if (!((rdy >> gn) & 1u) && ++sp > 4) __nanosleep(40);
                    }
                }
#pragma unroll
                for (int k8 = 0; k8 < 8; k8++) {
                    uint4 a = abuf[k8];
                    if (ch < 7) abuf[k8] = __ldcg(Ag + (8 * gn + k8) * 128 + tid);
                    int kcg = 8 * g + k8;
#pragma unroll
                    for (int q = 0; q < 4; q++) {
                        uint2 bv = *(const uint2*)&Wr_f[((q * 64 + kcg) * 32 + l) * 2];
                        mma_f16(acc[q][k8 & 1], a.x, a.y, a.z, a.w, bv.x, bv.y);
                    }
                }
            }

            // xz from SMEM ring
            const int s = t & 3;
            {
                int sp = 0;
                while (pflag[s] < t + 1) { if (++sp > 4) __nanosleep(40); }
            }
            __threadfence_block();
            const float* rs = ring + (size_t)s * 64 * 34;
            float2 xz[2][4];
#pragma unroll
            for (int r2 = 0; r2 < 2; r2++)
#pragma unroll
                for (int q = 0; q < 4; q++)
                    xz[r2][q] = *(const float2*)&rs[(b0 + 8 * r2) * 34 + q * 8 + j0];

            // gate phase (registers only)
#pragma unroll
            for (int r2 = 0; r2 < 2; r2++) {
                float hv[2];
#pragma unroll
                for (int d = 0; d < 2; d++) {
                    int idx = 2 * r2 + d;
                    float zi = acc[0][0][idx] + acc[0][1][idx] + (d ? xz[r2][0].y : xz[r2][0].x);
                    float zf = acc[1][0][idx] + acc[1][1][idx] + (d ? xz[r2][1].y : xz[r2][1].x);
                    float zg = acc[2][0][idx] + acc[2][1][idx] + (d ? xz[r2][2].y : xz[r2][2].x);
                    float zo = acc[3][0][idx] + acc[3][1][idx] + (d ? xz[r2][3].y : xz[r2][3].x);
                    float ig = sigmoid_fast(zi);
                    float fg = sigmoid_fast(zf);
                    float gg = tanh_fast(zg);
                    float og = sigmoid_fast(zo);
                    float cv = fg * cst[idx] + ig * gg;
                    cst[idx] = cv;
                    hv[d] = og * tanh_fast(cv);
                }
                hwrt[(kcg_w * 128 + tid) * 4 + 2 * hi_w + r2] = pack_f16(hv[0], hv[1]);
            }

            // warp-granular publish: h arrival (cross-CTA) + ring credit (CTA)
            __threadfence();
            __syncwarp();
            if (l == 0) {
                atomicAdd(&g_cnt[my_group * 32], 1u);
                atomicAdd_block(lcnt, 1);
            }
        }
    }
}

// ---------------------------------------------------------------------------
// Kernel 3a: logits partials. grid (8 kchunks, 64 rows); k-chunk = 128.
// ---------------------------------------------------------------------------
__device__ __forceinline__ float h_read_b0(int b, int u) {
    uint32_t v = g_h[((u >> 4) * 128 + (b >> 4) * 32 + (b & 7) * 4 + ((u & 7) >> 1)) * 4
                     + 2 * ((u >> 3) & 1) + ((b >> 3) & 1)];
    unsigned short bits = (u & 1) ? (unsigned short)(v >> 16)
                                  : (unsigned short)(v & 0xffffu);
    return __half2float(__ushort_as_half(bits));
}

__global__ __launch_bounds__(256) void logits_part(const float* __restrict__ Wd) {
    __shared__ float hk_s[128];
    const int kc  = blockIdx.x;
    const int b   = blockIdx.y;
    const int tid = threadIdx.x;
    const int k0  = kc * 128;
    if (tid < 128) hk_s[tid] = h_read_b0(b, k0 + tid);
    __syncthreads();

    if (tid < 250) {
        const int j0 = tid * 4;
        float acc[4] = {0.f, 0.f, 0.f, 0.f};
        const float* wp = Wd + (size_t)k0 * kC + j0;
#pragma unroll 8
        for (int k = 0; k < 128; k++) {
            float4 wv = *(const float4*)(wp + (size_t)k * kC);
            float  hk = hk_s[k];
            acc[0] = fmaf(hk, wv.x, acc[0]);
            acc[1] = fmaf(hk, wv.y, acc[1]);
            acc[2] = fmaf(hk, wv.z, acc[2]);
            acc[3] = fmaf(hk, wv.w, acc[3]);
        }
        *(float4*)&g_lpart[((size_t)kc * 64 + b) * kC + j0] =
            make_float4(acc[0], acc[1], acc[2], acc[3]);
    }
}

// ---------------------------------------------------------------------------
// Kernel 3b: softmax over summed partials (fixed-order, deterministic)
// ---------------------------------------------------------------------------
__global__ __launch_bounds__(256) void softmax_final(
    const float* __restrict__ bd, float* __restrict__ out) {
    __shared__ float red[256];
    const int b   = blockIdx.x;
    const int tid = threadIdx.x;
    const int j0  = tid * 4;
    const bool active = (j0 < kC);

    float acc[4] = {0.f, 0.f, 0.f, 0.f};
    if (active) {
#pragma unroll
        for (int p = 0; p < 8; p++) {
            float4 v = *(const float4*)&g_lpart[((size_t)p * 64 + b) * kC + j0];
            acc[0] += v.x; acc[1] += v.y; acc[2] += v.z; acc[3] += v.w;
        }
        float4 bv = *(const float4*)&bd[j0];
        acc[0] += bv.x; acc[1] += bv.y; acc[2] += bv.z; acc[3] += bv.w;
    }

    float m = active ? fmaxf(fmaxf(acc[0], acc[1]), fmaxf(acc[2], acc[3]))
                     : -INFINITY;
    red[tid] = m;
    __syncthreads();
    for (int s = 128; s > 0; s >>= 1) {
        if (tid < s) red[tid] = fmaxf(red[tid], red[tid + s]);
        __syncthreads();
    }
    float mx = red[0];
    __syncthreads();

    float e[4] = {0.f, 0.f, 0.f, 0.f};
    float psum = 0.f;
    if (active) {
#pragma unroll
        for (int cc = 0; cc < 4; cc++) { e[cc] = expf(acc[cc] - mx); psum += e[cc]; }
    }
    red[tid] = psum;
    __syncthreads();
    for (int s = 128; s > 0; s >>= 1) {
        if (tid < s) red[tid] += red[tid + s];
        __syncthreads();
    }
    float inv = 1.f / red[0];
    if (active) {
#pragma unroll
        for (int cc = 0; cc < 4; cc++) out[(size_t)b * kC + j0 + cc] = e[cc] * inv;
    }
}

// ---------------------------------------------------------------------------
// Launch
// ---------------------------------------------------------------------------
extern "C" void kernel_launch(void* const* d_in, const int* in_sizes, int n_in,
                              void* d_out, int out_size) {
    const float* x    = (const float*)d_in[0];
    const float* Wk   = (const float*)d_in[1];
    const float* Wr   = (const float*)d_in[2];
    const float* bias = (const float*)d_in[3];
    const float* Wd   = (const float*)d_in[4];
    const float* bd   = (const float*)d_in[5];
    float* out = (float*)d_out;

    const int smem_bytes = SMEM_U32 * (int)sizeof(uint32_t);   // 133280
    cudaFuncSetAttribute(lstm_fused, cudaFuncAttributeMaxDynamicSharedMemorySize,
                         smem_bytes);

    reset_kernel<<<64, 256>>>();
    permute_x<<<(int)((size_t)kT * 4096 / 256), 256>>>(x);
    lstm_fused<<<NCTA, NTHR, smem_bytes>>>(Wr, Wk, bias);
    logits_part<<<dim3(8, 64), 256>>>(Wd);
    softmax_final<<<kB, 256>>>(bd, out);
}

// round 16
// speedup vs baseline: 1.0290x; 1.0082x over previous
#include <cuda_runtime.h>
#include <cuda_fp16.h>
#include <math.h>
#include <stdint.h>

// Problem constants
static constexpr int kB  = 64;      // batch
static constexpr int kT  = 1024;    // time steps
static constexpr int kF  = 512;     // input features
static constexpr int kU  = 1024;    // hidden units
static constexpr int k4U = 4096;    // 4*U
static constexpr int kC  = 1000;    // classes

static constexpr int NCTA = 128;    // persistent CTAs (1/SM)
static constexpr int NTHR = 256;    // 8 warps: 0-3 consumers (LSTM), 4-7 producers (xz)

// SMEM layout (u32 units within dynamic smem)
static constexpr int OFF_WRF   = 0;        // Wr fp16 fragments: 16384 u32 (64 KB)
static constexpr int OFF_WKF   = 16384;    // Wk fp16 frags: 4096 uint2 = 8192 u32 (32 KB)
static constexpr int OFF_RING  = 24576;    // xz ring: 4 stages x 64 x 34 fp32 = 8704 u32
static constexpr int OFF_BIAS  = 33280;    // 32 fp32
static constexpr int OFF_FLAGS = 33312;    // pflag[4], lcnt
static constexpr int SMEM_U32  = 33320;    // 133280 bytes
// head phase reuses fsm[0..32832) for de-permuted h (64 rows x 513 u32, padded)

// Scratch (device globals: allocation-free per harness rules)
// x permuted to fp16 A-fragment order: idx(t,kcg,mt,lane) = t*4096 + kcg*128 + mt*32 + lane
__device__ uint4    g_xf[(size_t)kT * 4096];       // 67 MB
// h ping-pong, fp16, permuted into m16n8k16 A-fragment order (see R5 comment)
__device__ uint32_t g_h[2 * 32768];
// Per-group monotonic warp-arrival counters (64 arrivals/group/step)
__device__ unsigned g_cnt[8 * 32];
// logits (pre-bias), written by persistent kernel head phase
__device__ float    g_logits[64 * kC];

__device__ __forceinline__ uint32_t pack_f16(float lo, float hi) {
    uint32_t r;
    asm("cvt.rn.f16x2.f32 %0, %1, %2;" : "=r"(r) : "f"(hi), "f"(lo));
    return r;
}
__device__ __forceinline__ float tanh_fast(float x) {
    float r;
    asm("tanh.approx.f32 %0, %1;" : "=f"(r) : "f"(x));
    return r;
}
__device__ __forceinline__ float sigmoid_fast(float x) {
    return 1.f / (1.f + __expf(-x));
}
__device__ __forceinline__ void mma_f16(float c[4], uint32_t a0, uint32_t a1,
                                        uint32_t a2, uint32_t a3,
                                        uint32_t b0, uint32_t b1) {
    asm volatile(
        "mma.sync.aligned.m16n8k16.row.col.f32.f16.f16.f32 "
        "{%0,%1,%2,%3},{%4,%5,%6,%7},{%8,%9},{%0,%1,%2,%3};"
        : "+f"(c[0]), "+f"(c[1]), "+f"(c[2]), "+f"(c[3])
        : "r"(a0), "r"(a1), "r"(a2), "r"(a3), "r"(b0), "r"(b1));
}
__device__ __forceinline__ void bar_named(int id, int cnt) {
    asm volatile("bar.sync %0, %1;" :: "r"(id), "r"(cnt) : "memory");
}
__device__ __forceinline__ unsigned ld_acq(const unsigned* p) {
    unsigned v;
    asm volatile("ld.acquire.gpu.u32 %0, [%1];" : "=r"(v) : "l"(p) : "memory");
    return v;
}
// Warp-cooperative group-counter poll. Lanes 0-7 own one group counter each.
__device__ __forceinline__ unsigned poll_groups(int lane, unsigned tgt,
                                                unsigned rdy) {
    unsigned ok = 1u;
    if (lane < 8 && !((rdy >> lane) & 1u)) {
        unsigned v = ld_acq(&g_cnt[lane * 32]);
        ok = (v >= tgt) ? 1u : 0u;
    }
    return __ballot_sync(0xffffffffu, ok != 0u);
}

// ---------------------------------------------------------------------------
// Kernel 1: reset + permute x -> fp16 A-fragment order (one uint4 per thread)
// ---------------------------------------------------------------------------
__global__ __launch_bounds__(256) void permute_x(const float* __restrict__ x) {
    size_t idx = (size_t)blockIdx.x * 256 + threadIdx.x;   // < kT*4096
    // reset (folded): h buffer 0 + group counters
    if (idx < 32768) g_h[idx] = 0u;
    if (idx < 8 * 32) g_cnt[idx] = 0u;

    int lane = idx & 31;
    int mt   = (idx >> 5) & 3;
    int kcg  = (idx >> 7) & 31;
    int t    = (int)(idx >> 12);
    int r  = mt * 16 + (lane >> 2);                        // batch row
    int k2 = kcg * 16 + 2 * (lane & 3);
    const float* x0 = x + ((size_t)r * kT + t) * kF;
    const float* x8 = x + ((size_t)(r + 8) * kT + t) * kF;
    float2 v00 = *(const float2*)(x0 + k2);
    float2 v10 = *(const float2*)(x8 + k2);
    float2 v01 = *(const float2*)(x0 + k2 + 8);
    float2 v11 = *(const float2*)(x8 + k2 + 8);
    uint4 o;
    o.x = pack_f16(v00.x, v00.y);
    o.y = pack_f16(v10.x, v10.y);
    o.z = pack_f16(v01.x, v01.y);
    o.w = pack_f16(v11.x, v11.y);
    g_xf[idx] = o;
}

// ---------------------------------------------------------------------------
// Kernel 2: fused persistent LSTM (R15 structure, fp16) + in-kernel logits.
// Warps 0-3: recurrence mma + gates; warps 4-7: per-step xz (full K=512)
// into a 4-deep SMEM ring. Warp-granular publish, JIT group polling.
// After the t-loop: all 8 warps compute logits for classes [8*cta, 8*cta+8).
// ---------------------------------------------------------------------------
extern __shared__ uint32_t fsm[];

__global__ __launch_bounds__(NTHR, 1) void lstm_fused(
    const float* __restrict__ Wr, const float* __restrict__ Wk,
    const float* __restrict__ bias, const float* __restrict__ Wd) {
    uint32_t*      Wr_f  = fsm + OFF_WRF;
    uint2*         Wk_f  = (uint2*)(fsm + OFF_WKF);
    float*         ring  = (float*)(fsm + OFF_RING);     // [4][64][34]
    float*         bia_s = (float*)(fsm + OFF_BIAS);
    volatile int*  pflag = (volatile int*)(fsm + OFF_FLAGS);      // [4]
    int*           lcnt  = (int*)(fsm + OFF_FLAGS + 4);           // ring credits

    const int tid = threadIdx.x;
    const int wid = tid >> 5, lid = tid & 31;
    const int u_base = blockIdx.x * 8;
    const int my_group = blockIdx.x >> 4;

    // ---- cooperative init (all 8 warps) ----
    // Wr fp16 fragments (16384 u32)
    for (int i = 0; i < 64; i++) {
        int lin = tid + i * NTHR;
        int reg = lin & 1;
        int ll  = (lin >> 1) & 31;
        int kcg = (lin >> 6) & 63;
        int q   = (lin >> 12) & 3;
        int lg = ll >> 2, lq = ll & 3;
        int k  = kcg * 16 + 2 * lq + 8 * reg;
        int col = q * kU + u_base + lg;
        float v0 = Wr[(size_t)k * k4U + col];
        float v1 = Wr[(size_t)(k + 1) * k4U + col];
        Wr_f[((q * 64 + kcg) * 32 + ll) * 2 + reg] = pack_f16(v0, v1);
    }
    // Wk fp16 fragments (4096 uint2): all 32 kcg
    for (int i = 0; i < 16; i++) {
        int lin = tid + i * NTHR;
        int lane = lin & 31;
        int nt   = (lin >> 5) & 3;
        int kcg  = lin >> 7;
        int gcol = nt * kU + u_base + (lane >> 2);
        int k2   = kcg * 16 + 2 * (lane & 3);
        uint2 bv;
        bv.x = pack_f16(Wk[(size_t)k2 * k4U + gcol],
                        Wk[(size_t)(k2 + 1) * k4U + gcol]);
        bv.y = pack_f16(Wk[(size_t)(k2 + 8) * k4U + gcol],
                        Wk[(size_t)(k2 + 9) * k4U + gcol]);
        Wk_f[(kcg * 4 + nt) * 32 + lane] = bv;
    }
    if (tid < 32) bia_s[tid] = bias[(tid >> 3) * kU + u_base + (tid & 7)];
    if (tid < 4) pflag[tid] = 0;
    if (tid == 0) *lcnt = 0;
    __syncthreads();

    if (wid >= 4) {
        // ================= PRODUCER (warps 4-7): xz full K =================
        const int pw = wid - 4;              // M-subtile (16 batch rows)
        const int r  = pw * 16 + (lid >> 2);
        const int cl = 2 * (lid & 3);
        for (int tp = 0; tp < kT; tp++) {
            const int s = tp & 3;
            if (tp >= 4) {
                int sp = 0;
                int tgt = 4 * (tp - 3);
                while (*(volatile int*)lcnt < tgt) {
                    if (++sp > 4) __nanosleep(40);
                }
                __threadfence_block();
            }
            float cacc[4][4];
#pragma unroll
            for (int nt = 0; nt < 4; nt++)
#pragma unroll
                for (int k = 0; k < 4; k++) cacc[nt][k] = 0.f;

            const uint4* Ap = g_xf + (size_t)tp * 4096 + pw * 32 + lid;
            uint4 pbuf[4];
#pragma unroll
            for (int i = 0; i < 4; i++) pbuf[i] = __ldcg(Ap + i * 128);
#pragma unroll 4
            for (int kcg = 0; kcg < 32; kcg++) {
                uint4 a = pbuf[kcg & 3];
                if (kcg < 28) pbuf[kcg & 3] = __ldcg(Ap + (kcg + 4) * 128);
#pragma unroll
                for (int nt = 0; nt < 4; nt++) {
                    uint2 bv = Wk_f[(kcg * 4 + nt) * 32 + lid];
                    mma_f16(cacc[nt], a.x, a.y, a.z, a.w, bv.x, bv.y);
                }
            }
            // epilogue: bias + ring store
            float* rs = ring + (size_t)s * 64 * 34;
#pragma unroll
            for (int nt = 0; nt < 4; nt++) {
                int col = nt * 8 + cl;
                float bx = bia_s[col], by = bia_s[col + 1];
                float2 lo = make_float2(cacc[nt][0] + bx, cacc[nt][1] + by);
                float2 hi = make_float2(cacc[nt][2] + bx, cacc[nt][3] + by);
                *(float2*)&rs[(r)     * 34 + col] = lo;
                *(float2*)&rs[(r + 8) * 34 + col] = hi;
            }
            __threadfence_block();
            bar_named(3, 128);               // producer warps only
            if (tid == 128) pflag[s] = tp + 1;
        }
    } else {
        // ================= CONSUMER (warps 0-3) =================
        const int w = wid, l = lid;
        const int grp = l >> 2, qd = l & 3;
        const int b0 = w * 16 + grp;         // batch rows b0, b0+8
        const int j0 = 2 * qd;               // units j0, j0+1
        const int kcg_w = blockIdx.x >> 1;
        const int hi_w  = blockIdx.x & 1;

        float cst[4] = {0.f, 0.f, 0.f, 0.f};

        for (int t = 0; t < kT; t++) {
            const uint4* Ag = (const uint4*)(g_h + (size_t)(t & 1) * 32768);
            uint32_t*  hwrt = g_h + (size_t)((t + 1) & 1) * 32768;

            // Group-ready mask: warp-arrival counters, 64 per group per step.
            unsigned tgt = 64u * (unsigned)t;
            unsigned rdy = (t == 0) ? 0xffffffffu : 0u;
            const int g0 = my_group;
            {
                int sp = 0;
                while (!((rdy >> g0) & 1u)) {
                    rdy = poll_groups(l, tgt, rdy);
                    if (!((rdy >> g0) & 1u) && ++sp > 4) __nanosleep(40);
                }
            }

            float acc[4][2][4];
#pragma unroll
            for (int q = 0; q < 4; q++)
#pragma unroll
                for (int p = 0; p < 2; p++)
#pragma unroll
                    for (int k = 0; k < 4; k++) acc[q][p][k] = 0.f;

            uint4 abuf[8];
#pragma unroll
            for (int i = 0; i < 8; i++)
                abuf[i] = __ldcg(Ag + (8 * g0 + i) * 128 + tid);

            for (int ch = 0; ch < 8; ch++) {
                const int g  = (ch + my_group) & 7;
                const int gn = (g + 1) & 7;
                if (ch < 7) {
                    int sp = 0;
                    while (!((rdy >> gn) & 1u)) {
                        rdy = poll_groups(l, tgt, rdy);
                        if (!((rdy >> gn) & 1u) && ++sp > 4) __nanosleep(40);
                    }
                }
#pragma unroll
                for (int k8 = 0; k8 < 8; k8++) {
                    uint4 a = abuf[k8];
                    if (ch < 7) abuf[k8] = __ldcg(Ag + (8 * gn + k8) * 128 + tid);
                    int kcg = 8 * g + k8;
#pragma unroll
                    for (int q = 0; q < 4; q++) {
                        uint2 bv = *(const uint2*)&Wr_f[((q * 64 + kcg) * 32 + l) * 2];
                        mma_f16(acc[q][k8 & 1], a.x, a.y, a.z, a.w, bv.x, bv.y);
                    }
                }
            }

            // xz from SMEM ring
            const int s = t & 3;
            {
                int sp = 0;
                while (pflag[s] < t + 1) { if (++sp > 4) __nanosleep(40); }
            }
            __threadfence_block();
            const float* rs = ring + (size_t)s * 64 * 34;
            float2 xz[2][4];
#pragma unroll
            for (int r2 = 0; r2 < 2; r2++)
#pragma unroll
                for (int q = 0; q < 4; q++)
                    xz[r2][q] = *(const float2*)&rs[(b0 + 8 * r2) * 34 + q * 8 + j0];

            // gate phase (registers only)
#pragma unroll
            for (int r2 = 0; r2 < 2; r2++) {
                float hv[2];
#pragma unroll
                for (int d = 0; d < 2; d++) {
                    int idx = 2 * r2 + d;
                    float zi = acc[0][0][idx] + acc[0][1][idx] + (d ? xz[r2][0].y : xz[r2][0].x);
                    float zf = acc[1][0][idx] + acc[1][1][idx] + (d ? xz[r2][1].y : xz[r2][1].x);
                    float zg = acc[2][0][idx] + acc[2][1][idx] + (d ? xz[r2][2].y : xz[r2][2].x);
                    float zo = acc[3][0][idx] + acc[3][1][idx] + (d ? xz[r2][3].y : xz[r2][3].x);
                    float ig = sigmoid_fast(zi);
                    float fg = sigmoid_fast(zf);
                    float gg = tanh_fast(zg);
                    float og = sigmoid_fast(zo);
                    float cv = fg * cst[idx] + ig * gg;
                    cst[idx] = cv;
                    hv[d] = og * tanh_fast(cv);
                }
                hwrt[(kcg_w * 128 + tid) * 4 + 2 * hi_w + r2] = pack_f16(hv[0], hv[1]);
            }

            // warp-granular publish: h arrival (cross-CTA) + ring credit (CTA)
            __threadfence();
            __syncwarp();
            if (l == 0) {
                atomicAdd(&g_cnt[my_group * 32], 1u);
                atomicAdd_block(lcnt, 1);
            }
        }
    }

    // ================= HEAD: logits for classes [8*cta, 8*cta+8) =============
    __syncthreads();                         // join producer/consumer roles
    // Wait until every group has published all kT steps (one-shot in steady
    // state; 64 warp-arrivals per group per step).
    {
        unsigned rdy = 0u;
        int sp = 0;
        while (rdy != 0xffffffffu) {
            rdy = poll_groups(lid, 64u * (unsigned)kT, rdy);
            if (rdy != 0xffffffffu && ++sp > 4) __nanosleep(100);
        }
    }
    // Stage h (buffer 0, fp16 permuted) de-permuted into SMEM, row-major with
    // padded stride 513 u32 (bank = (b*513 + up) % 32 is lane-bijective).
    uint32_t* smem_h = fsm;                  // 64 * 513 = 32832 u32 (< SMEM_U32)
    for (int i = 0; i < 32768 / NTHR; i++) {
        int idx = tid + i * NTHR;
        uint32_t v = __ldcg(&g_h[idx]);      // buffer 0 = h(t=1024)
        int y  = idx >> 2;
        int b  = (((y >> 5) & 3) << 4) | ((idx & 1) << 3) | ((y >> 2) & 7);
        int up = ((y >> 7) << 3) | (((idx >> 1) & 1) << 2) | (y & 3);  // u>>1
        smem_h[b * 513 + up] = v;
    }
    __syncthreads();

    const int c = blockIdx.x * 8 + wid;      // this warp's class
    if (c < kC) {
        const uint32_t* h1 = smem_h + (size_t)lid * 513;        // row lid
        const uint32_t* h2 = smem_h + (size_t)(lid + 32) * 513; // row lid+32
        float a1 = 0.f, a2 = 0.f;
        for (int kb = 0; kb < kU; kb += 32) {
            // lanes load Wd[kb+l][c] in parallel (MLP=32), broadcast via shfl
            float wv = __ldg(&Wd[(size_t)(kb + lid) * kC + c]);
#pragma unroll
            for (int j = 0; j < 32; j += 2) {
                float w0 = __shfl_sync(0xffffffffu, wv, j);
                float w1 = __shfl_sync(0xffffffffu, wv, j + 1);
                uint32_t p1 = h1[(kb + j) >> 1];
                uint32_t p2 = h2[(kb + j) >> 1];
                __half2 q1 = *(__half2*)&p1;   // lo = even k
                __half2 q2 = *(__half2*)&p2;
                a1 = fmaf(__low2float(q1),  w0, a1);
                a1 = fmaf(__high2float(q1), w1, a1);
                a2 = fmaf(__low2float(q2),  w0, a2);
                a2 = fmaf(__high2float(q2), w1, a2);
            }
        }
        g_logits[(size_t)lid * kC + c]        = a1;
        g_logits[(size_t)(lid + 32) * kC + c] = a2;
    }
}

// ---------------------------------------------------------------------------
// Kernel 3: softmax over logits + bias (fixed-order, deterministic)
// ---------------------------------------------------------------------------
__global__ __launch_bounds__(256) void softmax_final(
    const float* __restrict__ bd, float* __restrict__ out) {
    __shared__ float red[256];
    const int b   = blockIdx.x;
    const int tid = threadIdx.x;
    const int j0  = tid * 4;
    const bool active = (j0 < kC);

    float acc[4] = {0.f, 0.f, 0.f, 0.f};
    if (active) {
        float4 v  = *(const float4*)&g_logits[(size_t)b * kC + j0];
        float4 bv = *(const float4*)&bd[j0];
        acc[0] = v.x + bv.x; acc[1] = v.y + bv.y;
        acc[2] = v.z + bv.z; acc[3] = v.w + bv.w;
    }

    float m = active ? fmaxf(fmaxf(acc[0], acc[1]), fmaxf(acc[2], acc[3]))
                     : -INFINITY;
    red[tid] = m;
    __syncthreads();
    for (int s = 128; s > 0; s >>= 1) {
        if (tid < s) red[tid] = fmaxf(red[tid], red[tid + s]);
        __syncthreads();
    }
    float mx = red[0];
    __syncthreads();

    float e[4] = {0.f, 0.f, 0.f, 0.f};
    float psum = 0.f;
    if (active) {
#pragma unroll
        for (int cc = 0; cc < 4; cc++) { e[cc] = expf(acc[cc] - mx); psum += e[cc]; }
    }
    red[tid] = psum;
    __syncthreads();
    for (int s = 128; s > 0; s >>= 1) {
        if (tid < s) red[tid] += red[tid + s];
        __syncthreads();
    }
    float inv = 1.f / red[0];
    if (active) {
#pragma unroll
        for (int cc = 0; cc < 4; cc++) out[(size_t)b * kC + j0 + cc] = e[cc] * inv;
    }
}

// ---------------------------------------------------------------------------
// Launch
// ---------------------------------------------------------------------------
extern "C" void kernel_launch(void* const* d_in, const int* in_sizes, int n_in,
                              void* d_out, int out_size) {
    const float* x    = (const float*)d_in[0];
    const float* Wk   = (const float*)d_in[1];
    const float* Wr   = (const float*)d_in[2];
    const float* bias = (const float*)d_in[3];
    const float* Wd   = (const float*)d_in[4];
    const float* bd   = (const float*)d_in[5];
    float* out = (float*)d_out;

    const int smem_bytes = SMEM_U32 * (int)sizeof(uint32_t);   // 133280
    cudaFuncSetAttribute(lstm_fused, cudaFuncAttributeMaxDynamicSharedMemorySize,
                         smem_bytes);

    permute_x<<<(int)((size_t)kT * 4096 / 256), 256>>>(x);
    lstm_fused<<<NCTA, NTHR, smem_bytes>>>(Wr, Wk, bias, Wd);
    softmax_final<<<kB, 256>>>(bd, out);
}